// round 7
// baseline (speedup 1.0000x reference)
#include <cuda_runtime.h>
#include <cuda_bf16.h>
#include <math.h>

// Problem constants (from reference setup_inputs)
#define NTOK   16384      // B*D = 4*4096
#define CDIM   320
#define PCACHE 32
#define RSEL   8
#define HEADS_ 8
#define DH     40
#define NKEY   9          // RSEL + 1

// ---------------- device scratch (static, no allocs) ----------------
__device__ float  d_P [NTOK * 3 * CDIM];                 // [q_now | k_now | v_now] (16384 x 960)
__device__ float  d_kpast[(size_t)NTOK * PCACHE * CDIM]; // full k_past (524288 x 320)
__device__ int    d_rowmap[NTOK * RSEL];                 // absolute cached-row index (t*32 + sel)
__device__ float  d_vsel[NTOK * RSEL * CDIM];            // selected v_past rows (131072 x 320)
__device__ float  d_ctx [NTOK * CDIM];                   // context before Wo
__device__ float2 d_rope[NKEY * (CDIM/2)];               // cos/sin per (pos, freq)

// ---------------- rope tables, fp32 libdevice semantics matching XLA ----------------
__global__ void rope_table_kernel()
{
    int idx = blockIdx.x * blockDim.x + threadIdx.x;
    if (idx >= NKEY * (CDIM/2)) return;
    int pos = idx / (CDIM/2);
    int ip  = idx - pos * (CDIM/2);
    float x   = __fdiv_rn((float)(2 * ip), (float)CDIM);
    float pw  = powf(10000.0f, x);           // libdevice powf (matches XLA pow lowering)
    float inv = __fdiv_rn(1.0f, pw);
    float ang = __fmul_rn((float)pos, inv);
    d_rope[idx] = make_float2(cosf(ang), sinf(ang));
}

// ---------------- fp32 GEMM, cublas-like: single accumulator, FMA, ascending k ------
// C = A(MxK) @ B(KxN) (+bias). BM=128 BN=64 BK=16, 256 threads, 8x4 per thread.
// Per output element: one fp32 accumulator, FMA, k strictly ascending — the same
// order cuBLAS SIMT SGEMM uses (bit-exact if cublas is single-accumulator).
template <bool GATHER, bool BIAS>
__global__ void __launch_bounds__(256)
gemm_fp32_kernel(const float* __restrict__ A, const float* __restrict__ B, float* __restrict__ C,
                 int Kdim, int lda, int ldb, int ldc,
                 const int* __restrict__ rowmap, const float* __restrict__ bias)
{
    const int BM = 128, BN = 64, BK = 16;
    __shared__ float As[BK][BM];
    __shared__ float Bs[BK][BN];

    int tid  = threadIdx.x;
    int row0 = blockIdx.x * BM;
    int col0 = blockIdx.y * BN;

    int ar  = tid >> 2;            // 0..63
    int akv = (tid & 3) * 4;       // 0,4,8,12
    int gr0 = row0 + ar, gr1 = row0 + ar + 64;
    if (GATHER) { gr0 = rowmap[gr0]; gr1 = rowmap[gr1]; }
    const float* ap0 = A + (size_t)gr0 * lda + akv;
    const float* ap1 = A + (size_t)gr1 * lda + akv;

    int br = tid >> 4;             // 0..15
    int bc = (tid & 15) * 4;       // 0..60
    const float* bp = B + (size_t)br * ldb + col0 + bc;

    int tx = tid & 15, ty = tid >> 4;
    float acc[8][4];
#pragma unroll
    for (int i = 0; i < 8; i++)
#pragma unroll
        for (int j = 0; j < 4; j++) acc[i][j] = 0.f;

    for (int k0 = 0; k0 < Kdim; k0 += BK) {
        float4 av0 = *reinterpret_cast<const float4*>(ap0 + k0);
        float4 av1 = *reinterpret_cast<const float4*>(ap1 + k0);
        float4 bv  = *reinterpret_cast<const float4*>(bp + (size_t)k0 * ldb);
        __syncthreads();
        As[akv + 0][ar]      = av0.x; As[akv + 1][ar]      = av0.y;
        As[akv + 2][ar]      = av0.z; As[akv + 3][ar]      = av0.w;
        As[akv + 0][ar + 64] = av1.x; As[akv + 1][ar + 64] = av1.y;
        As[akv + 2][ar + 64] = av1.z; As[akv + 3][ar + 64] = av1.w;
        Bs[br][bc + 0] = bv.x; Bs[br][bc + 1] = bv.y;
        Bs[br][bc + 2] = bv.z; Bs[br][bc + 3] = bv.w;
        __syncthreads();
#pragma unroll
        for (int kk = 0; kk < BK; kk++) {   // ascending k within tile, tiles ascending
            float4 a0 = *reinterpret_cast<const float4*>(&As[kk][ty * 4]);
            float4 a1 = *reinterpret_cast<const float4*>(&As[kk][64 + ty * 4]);
            float4 b4 = *reinterpret_cast<const float4*>(&Bs[kk][tx * 4]);
            float av[8] = {a0.x, a0.y, a0.z, a0.w, a1.x, a1.y, a1.z, a1.w};
            float bb[4] = {b4.x, b4.y, b4.z, b4.w};
#pragma unroll
            for (int i = 0; i < 8; i++)
#pragma unroll
                for (int j = 0; j < 4; j++)
                    acc[i][j] = __fmaf_rn(av[i], bb[j], acc[i][j]);
        }
    }

    int gc = col0 + tx * 4;
#pragma unroll
    for (int i = 0; i < 8; i++) {
        int r = row0 + ((i < 4) ? (ty * 4 + i) : (64 + ty * 4 + i - 4));
        float4 v = make_float4(acc[i][0], acc[i][1], acc[i][2], acc[i][3]);
        if (BIAS) {
            v.x = __fadd_rn(v.x, bias[gc + 0]); v.y = __fadd_rn(v.y, bias[gc + 1]);
            v.z = __fadd_rn(v.z, bias[gc + 2]); v.w = __fadd_rn(v.w, bias[gc + 3]);
        }
        *reinterpret_cast<float4*>(C + (size_t)r * ldc + gc) = v;
    }
}

// ---------------- scores: warp-per-dot, lane-strided (stride 32) + shfl tree --------
// Mirrors cublas gemv2T / XLA row-reduce lowering of einsum('nqc,npc->np'):
// lane l accumulates c = l, l+32, ..., serial FMA; then shuffle-down binary tree.
__global__ void __launch_bounds__(256)
scores_topk_kernel(int* __restrict__ rowmap)
{
    int t = blockIdx.x;
    __shared__ float qs[CDIM];
    __shared__ float sc[PCACHE];
    int tid = threadIdx.x;
    for (int i = tid; i < CDIM; i += 256) qs[i] = d_P[(size_t)t * 960 + i];
    __syncthreads();

    int w = tid >> 5, lane = tid & 31;
#pragma unroll
    for (int r = 0; r < 4; r++) {
        int p = w * 4 + r;
        const float* krow = d_kpast + ((size_t)t * PCACHE + p) * CDIM;
        float acc = 0.f;
#pragma unroll
        for (int i = 0; i < CDIM / 32; i++)      // 10 strided elements per lane, ascending
            acc = __fmaf_rn(qs[lane + 32 * i], krow[lane + 32 * i], acc);
#pragma unroll
        for (int off = 16; off; off >>= 1)       // binary tree, lane 0 holds result
            acc = __fadd_rn(acc, __shfl_down_sync(0xffffffffu, acc, off));
        if (lane == 0) sc[p] = acc;
    }
    __syncthreads();

    if (tid == 0) {
        unsigned used = 0;
#pragma unroll
        for (int j = 0; j < RSEL; j++) {
            float best = -3.402823466e38f; int bi = 0;
            for (int p = 0; p < PCACHE; p++) {
                if (!((used >> p) & 1u) && sc[p] > best) { best = sc[p]; bi = p; }
            }
            used |= (1u << bi);
            rowmap[t * RSEL + j] = t * PCACHE + bi;
        }
    }
}

// ---------------- attention: RoPE (mul/sub, no FMA), serial softmax, serial FMA ------
__global__ void __launch_bounds__(256)
attn_kernel(const int* __restrict__ rowmap)
{
    int t = blockIdx.x, tid = threadIdx.x;
    __shared__ float q[CDIM];
    __shared__ float kb[NKEY][CDIM];
    __shared__ float vb[NKEY][CDIM];
    __shared__ float sw[HEADS_][NKEY];
    __shared__ int rows[RSEL];

    if (tid < RSEL) rows[tid] = rowmap[t * RSEL + tid];
    for (int i = tid; i < CDIM; i += 256) q[i] = d_P[(size_t)t * 960 + i];
    __syncthreads();

    for (int i = tid; i < NKEY * CDIM; i += 256) {
        int j = i / CDIM, c = i - j * CDIM;
        kb[j][c] = (j < RSEL) ? d_kpast[(size_t)rows[j] * CDIM + c]
                              : d_P[(size_t)t * 960 + CDIM + c];       // k_now
        vb[j][c] = (j < RSEL) ? d_vsel[(size_t)(t * RSEL + j) * CDIM + c]
                              : d_P[(size_t)t * 960 + 2 * CDIM + c];   // v_now
    }
    __syncthreads();

    // RoPE on keys at position j (q at pos 0 is exact identity). mul/mul/sub|add, RN.
    for (int pidx = tid; pidx < NKEY * (CDIM/2); pidx += 256) {
        int j = pidx / (CDIM/2), ip = pidx - j * (CDIM/2);
        float2 cs = d_rope[j * (CDIM/2) + ip];
        float e = kb[j][2*ip], o = kb[j][2*ip + 1];
        kb[j][2*ip]     = __fsub_rn(__fmul_rn(e, cs.x), __fmul_rn(o, cs.y));
        kb[j][2*ip + 1] = __fadd_rn(__fmul_rn(e, cs.y), __fmul_rn(o, cs.x));
    }
    __syncthreads();

    // logits: serial ascending-d fp32 FMA, then * Dh^-0.5
    if (tid < HEADS_ * NKEY) {
        int h = tid / NKEY, j = tid - h * NKEY;
        float s = 0.f;
#pragma unroll
        for (int d = 0; d < DH; d++)
            s = __fmaf_rn(q[h * DH + d], kb[j][h * DH + d], s);
        sw[h][j] = __fmul_rn(s, 0.15811388300841897f);
    }
    __syncthreads();

    // softmax: serial ascending max / sum, exp via libdevice expf, divide
    if (tid < HEADS_) {
        int h = tid;
        float mx = sw[h][0];
#pragma unroll
        for (int j = 1; j < NKEY; j++) mx = fmaxf(mx, sw[h][j]);
        float e[NKEY]; float sum = 0.f;
#pragma unroll
        for (int j = 0; j < NKEY; j++) {
            e[j] = expf(__fsub_rn(sw[h][j], mx));
            sum = __fadd_rn(sum, e[j]);
        }
#pragma unroll
        for (int j = 0; j < NKEY; j++) sw[h][j] = __fdiv_rn(e[j], sum);
    }
    __syncthreads();

    // ctx = attn @ v: serial ascending-j fp32 FMA
    for (int c = tid; c < CDIM; c += 256) {
        int h = c / DH;
        float acc = 0.f;
#pragma unroll
        for (int j = 0; j < NKEY; j++)
            acc = __fmaf_rn(sw[h][j], vb[j][c], acc);
        d_ctx[(size_t)t * CDIM + c] = acc;
    }
}

// ---------------- launch ----------------
extern "C" void kernel_launch(void* const* d_in, const int* in_sizes, int n_in,
                              void* d_out, int out_size)
{
    const float* hidden = (const float*)d_in[0];
    const float* cached = (const float*)d_in[1];
    const float* Wq     = (const float*)d_in[2];
    const float* Wk     = (const float*)d_in[3];
    const float* Wv     = (const float*)d_in[4];
    const float* Wo     = (const float*)d_in[5];
    const float* bo     = (const float*)d_in[6];
    float* out = (float*)d_out;

    float *pP, *pKpast, *pVsel, *pCtx;
    int* pRow;
    cudaGetSymbolAddress((void**)&pP,     d_P);
    cudaGetSymbolAddress((void**)&pKpast, d_kpast);
    cudaGetSymbolAddress((void**)&pVsel,  d_vsel);
    cudaGetSymbolAddress((void**)&pCtx,   d_ctx);
    cudaGetSymbolAddress((void**)&pRow,   d_rowmap);

    rope_table_kernel<<<6, 256>>>();

    // q_now | k_now | v_now = hidden @ (Wq|Wk|Wv)  (column slices of d_P)
    gemm_fp32_kernel<false, false><<<dim3(NTOK/128, 5), 256>>>(
        hidden, Wq, pP + 0,        CDIM, CDIM, CDIM, 3 * CDIM, nullptr, nullptr);
    gemm_fp32_kernel<false, false><<<dim3(NTOK/128, 5), 256>>>(
        hidden, Wk, pP + CDIM,     CDIM, CDIM, CDIM, 3 * CDIM, nullptr, nullptr);
    gemm_fp32_kernel<false, false><<<dim3(NTOK/128, 5), 256>>>(
        hidden, Wv, pP + 2 * CDIM, CDIM, CDIM, CDIM, 3 * CDIM, nullptr, nullptr);

    // k_past = cached @ Wk   (524288 x 320)
    gemm_fp32_kernel<false, false><<<dim3(NTOK * PCACHE / 128, 5), 256>>>(
        cached, Wk, pKpast, CDIM, CDIM, CDIM, CDIM, nullptr, nullptr);

    // scores (gemv2T-order: strided-32 lanes + shuffle tree) + top-8 -> rowmap
    scores_topk_kernel<<<NTOK, 256>>>(pRow);

    // v_sel = cached[rowmap] @ Wv   (131072 x 320) — bit-same as gathering full v_past
    gemm_fp32_kernel<true, false><<<dim3(NTOK * RSEL / 128, 5), 256>>>(
        cached, Wv, pVsel, CDIM, CDIM, CDIM, CDIM, pRow, nullptr);

    // RoPE + attention + ctx
    attn_kernel<<<NTOK, 256>>>(pRow);

    // out = ctx @ Wo + bo
    gemm_fp32_kernel<false, true><<<dim3(NTOK/128, 5), 256>>>(
        pCtx, Wo, out, CDIM, CDIM, CDIM, CDIM, nullptr, bo);
}